// round 6
// baseline (speedup 1.0000x reference)
#include <cuda_runtime.h>
#include <cstdint>
#include <cstddef>

// Problem constants
#define NM 4
#define NB 2048
#define ND 1024
#define NE 8
#define NO 1024
#define NC 2

// Scratch (no allocations allowed)
__device__ float g_vtab[ND * NE * NC];   // [d][e*2+c]  64 KB
__device__ float g_bdot[NE * NC];        // 16 floats

// packed f32x2 FMA (sm_100a+; ptxas never auto-fuses this)
#define FMA_F32X2(acc, a, b) \
    asm("fma.rn.f32x2 %0, %1, %2, %0;" : "+l"(acc) : "l"(a), "l"(b))
#define BCAST_F32X2(dst, f) \
    asm("mov.b64 %0, {%1, %1};" : "=l"(dst) : "f"(f))
#define UNPACK_F32X2(lo, hi, in) \
    asm("mov.b64 {%0, %1}, %2;" : "=f"(lo), "=f"(hi) : "l"(in))

// ---------------------------------------------------------------------------
// Pass A: V[e,d,c] = sum_o expert_w[e,d,o] * head_w[o,c]
// 1024 blocks x 256 threads, one row per warp (max MLP). bdot fused.
// Measured ~4us, near the 32MB stream floor. Unchanged.
// ---------------------------------------------------------------------------
__global__ void __launch_bounds__(256) build_vtab_kernel(
    const float* __restrict__ expert_w,
    const float* __restrict__ head_w,
    const float* __restrict__ expert_b)
{
    __shared__ float hw[NO * NC];  // 2048 floats, [o*2+c]
    for (int i = threadIdx.x; i < NO * NC; i += 256) hw[i] = head_w[i];
    __syncthreads();

    const int lane = threadIdx.x & 31;
    const int wid  = threadIdx.x >> 5;
    const int r    = (blockIdx.x << 3) + wid;          // row = e*1024 + d

    const float4* row4 = (const float4*)(expert_w + ((size_t)r << 10));
    float4 w[8];
#pragma unroll
    for (int i = 0; i < 8; i++) w[i] = row4[i * 32 + lane];

    float a0 = 0.f, a1 = 0.f;
#pragma unroll
    for (int i = 0; i < 8; i++) {
        const float4* h = (const float4*)(hw + ((i * 128 + lane * 4) << 1));
        float4 h0 = h[0], h1 = h[1];
        a0 += w[i].x * h0.x + w[i].y * h0.z + w[i].z * h1.x + w[i].w * h1.z;
        a1 += w[i].x * h0.y + w[i].y * h0.w + w[i].z * h1.y + w[i].w * h1.w;
    }
#pragma unroll
    for (int off = 16; off; off >>= 1) {
        a0 += __shfl_down_sync(0xffffffffu, a0, off);
        a1 += __shfl_down_sync(0xffffffffu, a1, off);
    }
    if (lane == 0) {
        int e = r >> 10, d = r & 1023;
        g_vtab[(d << 4) + (e << 1) + 0] = a0;
        g_vtab[(d << 4) + (e << 1) + 1] = a1;
    }

    if (blockIdx.x < 8 && wid == 0) {
        int e = blockIdx.x;
        const float4* eb4 = ((const float4*)expert_b) + (e << 8);
        float b0 = 0.f, b1 = 0.f;
#pragma unroll
        for (int i = 0; i < 8; i++) {
            float4 bb = eb4[i * 32 + lane];
            const float4* h = (const float4*)(hw + ((i * 32 + lane) << 3));
            float4 h0 = h[0], h1 = h[1];
            b0 += bb.x * h0.x + bb.y * h0.z + bb.z * h1.x + bb.w * h1.z;
            b1 += bb.x * h0.y + bb.y * h0.w + bb.z * h1.y + bb.w * h1.w;
        }
#pragma unroll
        for (int off = 16; off; off >>= 1) {
            b0 += __shfl_down_sync(0xffffffffu, b0, off);
            b1 += __shfl_down_sync(0xffffffffu, b1, off);
        }
        if (lane == 0) { g_bdot[e * 2] = b0; g_bdot[e * 2 + 1] = b1; }
    }
}

// ---------------------------------------------------------------------------
// Main fused pass, round 6: 2 resident blocks per SM (independent barrier
// domains -> staging of one block overlaps compute of the other), 128-reg
// budget (ptxas can batch ALL table loads), register-prefetched x stream.
//
// 256 blocks x 256 threads (__launch_bounds__(256,2)). Block = 8 b x 4 m
// = 32 tokens. Thread (s, t): t = tid&31 token, s = tid>>5 d-slice (8
// slices). Combined table ct[d][24] = {gate_w[d][0..7], V[d][0..15]},
// read as warp-uniform broadcast LDS.128. 16 chunks x 64 cols; next
// chunk's LDG issues before the compute block (latency hidden).
// Cross-slice reduction: ping-pong fold 8->4->2->1 in a 2112-float buffer.
// Smem 104.3 KB -> 2 blocks/SM.
// ---------------------------------------------------------------------------
#define XSTR 66    // (2t+c) mod 32 -> 2-way worst case on x reads; float2 aligned
#define RSTR 25

__global__ void __launch_bounds__(256, 2) moe_main_kernel(
    const float* __restrict__ x,
    const float* __restrict__ gate_w,
    const float* __restrict__ gate_b,
    const float* __restrict__ head_b,
    float* __restrict__ out)
{
    extern __shared__ float sm[];
    float* ct = sm;                    // 24576 floats: [d][24] = gate(8) | V(16)
    float* xs = sm + 24576;            // 32 * 66 = 2112 floats: x tile (1 chunk)
    float* rr = xs;                    // reduction buffer aliases xs (64*25=1600 <= 2112)

    const int tid = threadIdx.x;
    const int b0  = blockIdx.x << 3;   // 8 b-values per block
    const int t   = tid & 31;          // token: m = t&3, brel = t>>2
    const int s   = tid >> 5;          // d-slice 0..7 (warp-uniform)

    // ---- fill combined table (coalesced float4 reads) ----
    {
        const float4* gsrc = (const float4*)gate_w;   // 2048 float4
        float4* cd = (float4*)ct;
        for (int i = tid; i < 2048; i += 256) {
            int d = i >> 1, h = i & 1;                // ct[d][0..7]
            cd[d * 6 + h] = gsrc[i];
        }
        const float4* vsrc = (const float4*)g_vtab;   // 4096 float4
        for (int i = tid; i < 4096; i += 256) {
            int d = i >> 2, q = i & 3;                // ct[d][8..23]
            cd[d * 6 + 2 + q] = vsrc[i];
        }
    }

    // ---- per-thread staging addresses (fixed; only chunk offset varies) ----
    // v in {tid, tid+256}: r = v>>4 (row 0..31), c4 = v&15 (float4 col)
    const int r0 = tid >> 4,          c40 = tid & 15;
    const int r1 = (tid + 256) >> 4,  c41 = tid & 15;
    const float* gp0 = x + ((size_t)((r0 & 3) << 11) + b0 + (r0 >> 2)) * ND + (c40 << 2);
    const float* gp1 = x + ((size_t)((r1 & 3) << 11) + b0 + (r1 >> 2)) * ND + (c41 << 2);
    float* sd0 = xs + r0 * XSTR + (c40 << 2);
    float* sd1 = xs + r1 * XSTR + (c41 << 2);

    unsigned long long acc[12];
#pragma unroll
    for (int k = 0; k < 12; k++) acc[k] = 0ull;

    // prologue: prefetch chunk 0
    float4 pf0 = *(const float4*)(gp0);
    float4 pf1 = *(const float4*)(gp1);

    for (int ch = 0; ch < 16; ch++) {
        __syncthreads();               // previous compute done (and table fill, 1st iter)
        *(float2*)(sd0)     = make_float2(pf0.x, pf0.y);
        *(float2*)(sd0 + 2) = make_float2(pf0.z, pf0.w);
        *(float2*)(sd1)     = make_float2(pf1.x, pf1.y);
        *(float2*)(sd1 + 2) = make_float2(pf1.z, pf1.w);
        if (ch < 15) {                 // prefetch next chunk; latency hides under compute
            pf0 = *(const float4*)(gp0 + (ch + 1) * 64);
            pf1 = *(const float4*)(gp1 + (ch + 1) * 64);
        }
        __syncthreads();               // xs visible

        const float* xrow = xs + t * XSTR + (s << 3);
        const int dg0 = (ch << 6) + (s << 3);
#pragma unroll
        for (int j = 0; j < 8; j += 2) {
            float2 xv = *(const float2*)(xrow + j);
            unsigned long long x0, x1;
            BCAST_F32X2(x0, xv.x);
            BCAST_F32X2(x1, xv.y);
            const ulonglong2* c0 = (const ulonglong2*)(ct + (dg0 + j) * 24);
            const ulonglong2* c1 = (const ulonglong2*)(ct + (dg0 + j + 1) * 24);
            ulonglong2 p0 = c0[0], p1 = c0[1], p2 = c0[2];
            ulonglong2 p3 = c0[3], p4 = c0[4], p5 = c0[5];
            FMA_F32X2(acc[0],  x0, p0.x); FMA_F32X2(acc[1],  x0, p0.y);
            FMA_F32X2(acc[2],  x0, p1.x); FMA_F32X2(acc[3],  x0, p1.y);
            FMA_F32X2(acc[4],  x0, p2.x); FMA_F32X2(acc[5],  x0, p2.y);
            FMA_F32X2(acc[6],  x0, p3.x); FMA_F32X2(acc[7],  x0, p3.y);
            FMA_F32X2(acc[8],  x0, p4.x); FMA_F32X2(acc[9],  x0, p4.y);
            FMA_F32X2(acc[10], x0, p5.x); FMA_F32X2(acc[11], x0, p5.y);
            ulonglong2 q0 = c1[0], q1 = c1[1], q2 = c1[2];
            ulonglong2 q3 = c1[3], q4 = c1[4], q5 = c1[5];
            FMA_F32X2(acc[0],  x1, q0.x); FMA_F32X2(acc[1],  x1, q0.y);
            FMA_F32X2(acc[2],  x1, q1.x); FMA_F32X2(acc[3],  x1, q1.y);
            FMA_F32X2(acc[4],  x1, q2.x); FMA_F32X2(acc[5],  x1, q2.y);
            FMA_F32X2(acc[6],  x1, q3.x); FMA_F32X2(acc[7],  x1, q3.y);
            FMA_F32X2(acc[8],  x1, q4.x); FMA_F32X2(acc[9],  x1, q4.y);
            FMA_F32X2(acc[10], x1, q5.x); FMA_F32X2(acc[11], x1, q5.y);
        }
    }

    // ---- ping-pong cross-slice fold: 8 -> 4 -> 2 -> 1 (in rr, 64 rows) ----
    float c[24];
#pragma unroll
    for (int k = 0; k < 12; k++) UNPACK_F32X2(c[2 * k], c[2 * k + 1], acc[k]);

    __syncthreads();                   // xs reads done; rr (alias) writable
    if (s == 4 || s == 5) {            // P1: spill slices 4,5
        float* rp = rr + ((s - 4) * 32 + t) * RSTR;
#pragma unroll
        for (int k = 0; k < 24; k++) rp[k] = c[k];
    }
    __syncthreads();
    if (s == 0 || s == 1) {            // P2: s0+=s4, s1+=s5
        const float* rp = rr + (s * 32 + t) * RSTR;
#pragma unroll
        for (int k = 0; k < 24; k++) c[k] += rp[k];
    }
    __syncthreads();
    if (s == 6 || s == 7) {            // P3: spill slices 6,7
        float* rp = rr + ((s - 6) * 32 + t) * RSTR;
#pragma unroll
        for (int k = 0; k < 24; k++) rp[k] = c[k];
    }
    __syncthreads();
    if (s == 2 || s == 3) {            // P4: s2+=s6, s3+=s7
        const float* rp = rr + ((s - 2) * 32 + t) * RSTR;
#pragma unroll
        for (int k = 0; k < 24; k++) c[k] += rp[k];
    }
    __syncthreads();
    if (s == 2 || s == 3) {            // P5: spill combined s2,s3
        float* rp = rr + ((s - 2) * 32 + t) * RSTR;
#pragma unroll
        for (int k = 0; k < 24; k++) rp[k] = c[k];
    }
    __syncthreads();
    if (s == 0 || s == 1) {            // P6: s0+=s2c, s1+=s3c
        const float* rp = rr + (s * 32 + t) * RSTR;
#pragma unroll
        for (int k = 0; k < 24; k++) c[k] += rp[k];
    }
    __syncthreads();
    if (s == 1) {                      // P7: spill combined s1
        float* rp = rr + t * RSTR;
#pragma unroll
        for (int k = 0; k < 24; k++) rp[k] = c[k];
    }
    __syncthreads();
    if (s == 0) {                      // P8: final sum + winner + output (warp 0)
        const float* rp = rr + t * RSTR;
#pragma unroll
        for (int k = 0; k < 24; k++) c[k] += rp[k];

        // gate logits (+bias); winner = max index among top-2 (ref semantics)
        float g[8];
#pragma unroll
        for (int e = 0; e < 8; e++) g[e] = c[e] + gate_b[e];
        int i1 = 0; float m1 = g[0];
#pragma unroll
        for (int e = 1; e < 8; e++) if (g[e] > m1) { m1 = g[e]; i1 = e; }
        int i2 = 0; float m2 = -3.402823466e38f;
#pragma unroll
        for (int e = 0; e < 8; e++) if (e != i1 && g[e] > m2) { m2 = g[e]; i2 = e; }
        int w = (i1 > i2) ? i1 : i2;

        float o0 = c[8 + (w << 1) + 0] + g_bdot[(w << 1) + 0];
        float o1 = c[8 + (w << 1) + 1] + g_bdot[(w << 1) + 1];

        // modality mean: tokens t..t+3 share brel, m = t&3 (consecutive lanes)
        o0 += __shfl_down_sync(0xffffffffu, o0, 2);
        o0 += __shfl_down_sync(0xffffffffu, o0, 1);
        o1 += __shfl_down_sync(0xffffffffu, o1, 2);
        o1 += __shfl_down_sync(0xffffffffu, o1, 1);

        if ((t & 3) == 0) {
            int b = b0 + (t >> 2);
            out[(b << 1) + 0] = 0.25f * o0 + head_b[0];
            out[(b << 1) + 1] = 0.25f * o1 + head_b[1];
        }
    }
}

// ---------------------------------------------------------------------------
extern "C" void kernel_launch(void* const* d_in, const int* in_sizes, int n_in,
                              void* d_out, int out_size)
{
    const float* x        = (const float*)d_in[0];
    const float* gate_w   = (const float*)d_in[1];
    const float* gate_b   = (const float*)d_in[2];
    const float* expert_w = (const float*)d_in[3];
    const float* expert_b = (const float*)d_in[4];
    const float* head_w   = (const float*)d_in[5];
    const float* head_b   = (const float*)d_in[6];
    float* out = (float*)d_out;

    const size_t SMEM = (24576 + 32 * XSTR) * sizeof(float);   // 106,752 B
    cudaFuncSetAttribute(moe_main_kernel,
                         cudaFuncAttributeMaxDynamicSharedMemorySize, (int)SMEM);

    build_vtab_kernel<<<1024, 256>>>(expert_w, head_w, expert_b);
    moe_main_kernel<<<256, 256, SMEM>>>(x, gate_w, gate_b, head_b, out);
}

// round 7
// speedup vs baseline: 1.1136x; 1.1136x over previous
#include <cuda_runtime.h>
#include <cstdint>
#include <cstddef>

// Problem constants
#define NM 4
#define NB 2048
#define ND 1024
#define NE 8
#define NO 1024
#define NC 2

#define DSPLIT 4          // D split across blocks
#define DLOC   256        // d-columns per block
#define NCH    4          // chunks per block
#define CHC    64         // cols per chunk
#define XSTR   66         // x-tile row stride (floats)

// Scratch (no allocations allowed)
__device__ float g_vtab[ND * NE * NC];          // [d][e*2+c]  64 KB
__device__ float g_bdot[NE * NC];               // 16 floats
__device__ float g_part[DSPLIT * NM * NB * 24]; // partials [split][tok][24]  3.1 MB

// packed f32x2 FMA (sm_100a+; ptxas never auto-fuses this)
#define FMA_F32X2(acc, a, b) \
    asm("fma.rn.f32x2 %0, %1, %2, %0;" : "+l"(acc) : "l"(a), "l"(b))
#define BCAST_F32X2(dst, f) \
    asm("mov.b64 %0, {%1, %1};" : "=l"(dst) : "f"(f))
#define UNPACK_F32X2(lo, hi, in) \
    asm("mov.b64 {%0, %1}, %2;" : "=f"(lo), "=f"(hi) : "l"(in))

// ---------------------------------------------------------------------------
// Pass A: V[e,d,c] = sum_o expert_w[e,d,o] * head_w[o,c]
// 1024 blocks x 256 threads, one row per warp. bdot fused. ~4.5us (measured).
// ---------------------------------------------------------------------------
__global__ void __launch_bounds__(256) build_vtab_kernel(
    const float* __restrict__ expert_w,
    const float* __restrict__ head_w,
    const float* __restrict__ expert_b)
{
    __shared__ float hw[NO * NC];  // [o*2+c]
    for (int i = threadIdx.x; i < NO * NC; i += 256) hw[i] = head_w[i];
    __syncthreads();

    const int lane = threadIdx.x & 31;
    const int wid  = threadIdx.x >> 5;
    const int r    = (blockIdx.x << 3) + wid;          // row = e*1024 + d

    const float4* row4 = (const float4*)(expert_w + ((size_t)r << 10));
    float4 w[8];
#pragma unroll
    for (int i = 0; i < 8; i++) w[i] = row4[i * 32 + lane];

    float a0 = 0.f, a1 = 0.f;
#pragma unroll
    for (int i = 0; i < 8; i++) {
        const float4* h = (const float4*)(hw + ((i * 128 + lane * 4) << 1));
        float4 h0 = h[0], h1 = h[1];
        a0 += w[i].x * h0.x + w[i].y * h0.z + w[i].z * h1.x + w[i].w * h1.z;
        a1 += w[i].x * h0.y + w[i].y * h0.w + w[i].z * h1.y + w[i].w * h1.w;
    }
#pragma unroll
    for (int off = 16; off; off >>= 1) {
        a0 += __shfl_down_sync(0xffffffffu, a0, off);
        a1 += __shfl_down_sync(0xffffffffu, a1, off);
    }
    if (lane == 0) {
        int e = r >> 10, d = r & 1023;
        g_vtab[(d << 4) + (e << 1) + 0] = a0;
        g_vtab[(d << 4) + (e << 1) + 1] = a1;
    }

    if (blockIdx.x < 8 && wid == 0) {
        int e = blockIdx.x;
        const float4* eb4 = ((const float4*)expert_b) + (e << 8);
        float b0 = 0.f, b1 = 0.f;
#pragma unroll
        for (int i = 0; i < 8; i++) {
            float4 bb = eb4[i * 32 + lane];
            const float4* h = (const float4*)(hw + ((i * 32 + lane) << 3));
            float4 h0 = h[0], h1 = h[1];
            b0 += bb.x * h0.x + bb.y * h0.z + bb.z * h1.x + bb.w * h1.z;
            b1 += bb.x * h0.y + bb.y * h0.w + bb.z * h1.y + bb.w * h1.w;
        }
#pragma unroll
        for (int off = 16; off; off >>= 1) {
            b0 += __shfl_down_sync(0xffffffffu, b0, off);
            b1 += __shfl_down_sync(0xffffffffu, b1, off);
        }
        if (lane == 0) { g_bdot[e * 2] = b0; g_bdot[e * 2 + 1] = b1; }
    }
}

// ---------------------------------------------------------------------------
// Main pass, round 7: D-SPLIT across blocks. Every round measured
// issue% == occ% (warps fully latency-stalled; residency is the wall).
// Shrinking the broadcast table to a 256-d slice (24 KB) + double-buffered
// x tile (33 KB) = 57 KB smem -> 3 blocks/SM = 24 warps (was 16).
//
// Grid 512 = 128 token-groups x 4 d-splits, 256 threads. Block = 64 tokens
// (16 b x 4 m) x 256 d. Thread (s,t): s = tid>>5 d-slice (8 x 32d), t =
// tid&31; 2 tokens per thread (A=t, B=t+32) so 12 broadcast LDS.128 feed
// 48 FFMA2 (round-5 winning ratio). Per-block partial sums (24/token) go
// to g_part; reduce_kernel folds the 4 splits + winner + m-mean + head.
// ---------------------------------------------------------------------------
__global__ void __launch_bounds__(256, 3) moe_main_kernel(
    const float* __restrict__ x,
    const float* __restrict__ gate_w)
{
    extern __shared__ float sm[];
    float* ct  = sm;                   // 6144 floats: [d_loc][24] = gate(8)|V(16)
    float* xs0 = sm + 6144;            // 64*66 = 4224 floats
    float* xs1 = sm + 6144 + 4224;
    float* rr  = sm;                   // fold buffer aliases everything (all dead)

    const int tid = threadIdx.x;
    const int tg  = blockIdx.x >> 2;        // token group 0..127
    const int ds  = blockIdx.x & 3;         // d-split 0..3
    const int b0  = tg << 4;                // 16 b-values
    const int dof = ds * DLOC;              // d offset
    const int t   = tid & 31;               // token lane (A=t, B=t+32)
    const int s   = tid >> 5;               // d-slice 0..7 (warp-uniform)

    // ---- fill table slice: gate_w rows dof..dof+255 -> ct[d][0..7],
    //      g_vtab rows -> ct[d][8..23] (coalesced float4) ----
    {
        const float4* gsrc = (const float4*)gate_w;     // [d][8] = 2 float4/row
        for (int i = tid; i < 512; i += 256) {
            int d = i >> 1, h = i & 1;
            *(float4*)(ct + d * 24 + h * 4) = gsrc[((dof + d) << 1) + h];
        }
        const float4* vsrc = (const float4*)g_vtab;     // [d][16] = 4 float4/row
        for (int i = tid; i < 1024; i += 256) {
            int d = i >> 2, q = i & 3;
            *(float4*)(ct + d * 24 + 8 + q * 4) = vsrc[((dof + d) << 2) + q];
        }
    }

    // ---- fixed staging addresses: 4 float4 per thread per chunk ----
    const float* gp[4];
    float* sd[4];
#pragma unroll
    for (int i = 0; i < 4; i++) {
        int idx = tid + i * 256;            // 0..1023
        int r = idx >> 4, c4 = idx & 15;    // row 0..63, float4 col 0..15
        int grow = ((r & 3) << 11) + b0 + (r >> 2);     // m*2048 + b0 + brel
        gp[i] = x + (size_t)grow * ND + dof + (c4 << 2);
        sd[i] = (float*)0 + r * XSTR + (c4 << 2);       // offset only
    }

    unsigned long long accA[12], accB[12];
#pragma unroll
    for (int k = 0; k < 12; k++) { accA[k] = 0ull; accB[k] = 0ull; }

    // prologue: stage chunk 0 into xs0
#pragma unroll
    for (int i = 0; i < 4; i++) {
        float4 v = *(const float4*)(gp[i]);
        float* dst = xs0 + (size_t)(sd[i] - (float*)0);
        *(float2*)(dst)     = make_float2(v.x, v.y);
        *(float2*)(dst + 2) = make_float2(v.z, v.w);
    }
    __syncthreads();   // chunk0 visible; table fill also complete

    for (int ch = 0; ch < NCH; ch++) {
        float* cur = (ch & 1) ? xs1 : xs0;
        float* nxt = (ch & 1) ? xs0 : xs1;

        // stage next chunk (nxt was fully consumed before last barrier)
        if (ch < NCH - 1) {
#pragma unroll
            for (int i = 0; i < 4; i++) {
                float4 v = *(const float4*)(gp[i] + (ch + 1) * CHC);
                float* dst = nxt + (size_t)(sd[i] - (float*)0);
                *(float2*)(dst)     = make_float2(v.x, v.y);
                *(float2*)(dst + 2) = make_float2(v.z, v.w);
            }
        }

        const float* xA = cur + t * XSTR + (s << 3);
        const float* xB = xA + 32 * XSTR;
        const int dl0 = (ch << 6) + (s << 3);           // local d base (0..255)
#pragma unroll
        for (int j = 0; j < 8; j += 2) {
            float2 xa = *(const float2*)(xA + j);
            float2 xb = *(const float2*)(xB + j);
            unsigned long long a0, a1, bp0, bp1;
            BCAST_F32X2(a0, xa.x);  BCAST_F32X2(a1, xa.y);
            BCAST_F32X2(bp0, xb.x); BCAST_F32X2(bp1, xb.y);
            const ulonglong2* c0 = (const ulonglong2*)(ct + (dl0 + j) * 24);
            const ulonglong2* c1 = (const ulonglong2*)(ct + (dl0 + j + 1) * 24);
            {
                ulonglong2 p0 = c0[0], p1 = c0[1], p2 = c0[2];
                ulonglong2 p3 = c0[3], p4 = c0[4], p5 = c0[5];
                FMA_F32X2(accA[0],  a0, p0.x); FMA_F32X2(accA[1],  a0, p0.y);
                FMA_F32X2(accA[2],  a0, p1.x); FMA_F32X2(accA[3],  a0, p1.y);
                FMA_F32X2(accA[4],  a0, p2.x); FMA_F32X2(accA[5],  a0, p2.y);
                FMA_F32X2(accA[6],  a0, p3.x); FMA_F32X2(accA[7],  a0, p3.y);
                FMA_F32X2(accA[8],  a0, p4.x); FMA_F32X2(accA[9],  a0, p4.y);
                FMA_F32X2(accA[10], a0, p5.x); FMA_F32X2(accA[11], a0, p5.y);
                FMA_F32X2(accB[0],  bp0, p0.x); FMA_F32X2(accB[1],  bp0, p0.y);
                FMA_F32X2(accB[2],  bp0, p1.x); FMA_F32X2(accB[3],  bp0, p1.y);
                FMA_F32X2(accB[4],  bp0, p2.x); FMA_F32X2(accB[5],  bp0, p2.y);
                FMA_F32X2(accB[6],  bp0, p3.x); FMA_F32X2(accB[7],  bp0, p3.y);
                FMA_F32X2(accB[8],  bp0, p4.x); FMA_F32X2(accB[9],  bp0, p4.y);
                FMA_F32X2(accB[10], bp0, p5.x); FMA_F32X2(accB[11], bp0, p5.y);
            }
            {
                ulonglong2 q0 = c1[0], q1 = c1[1], q2 = c1[2];
                ulonglong2 q3 = c1[3], q4 = c1[4], q5 = c1[5];
                FMA_F32X2(accA[0],  a1, q0.x); FMA_F32X2(accA[1],  a1, q0.y);
                FMA_F32X2(accA[2],  a1, q1.x); FMA_F32X2(accA[3],  a1, q1.y);
                FMA_F32X2(accA[4],  a1, q2.x); FMA_F32X2(accA[5],  a1, q2.y);
                FMA_F32X2(accA[6],  a1, q3.x); FMA_F32X2(accA[7],  a1, q3.y);
                FMA_F32X2(accA[8],  a1, q4.x); FMA_F32X2(accA[9],  a1, q4.y);
                FMA_F32X2(accA[10], a1, q5.x); FMA_F32X2(accA[11], a1, q5.y);
                FMA_F32X2(accB[0],  bp1, q0.x); FMA_F32X2(accB[1],  bp1, q0.y);
                FMA_F32X2(accB[2],  bp1, q1.x); FMA_F32X2(accB[3],  bp1, q1.y);
                FMA_F32X2(accB[4],  bp1, q2.x); FMA_F32X2(accB[5],  bp1, q2.y);
                FMA_F32X2(accB[6],  bp1, q3.x); FMA_F32X2(accB[7],  bp1, q3.y);
                FMA_F32X2(accB[8],  bp1, q4.x); FMA_F32X2(accB[9],  bp1, q4.y);
                FMA_F32X2(accB[10], bp1, q5.x); FMA_F32X2(accB[11], bp1, q5.y);
            }
        }
        __syncthreads();   // staging visible + cur fully consumed
    }

    // ---- fold 8 slices via smem (rr aliases table + x buffers, all dead) ----
    {
        float* rp = rr + (s * 32 + t) * 49;
#pragma unroll
        for (int k = 0; k < 12; k++) UNPACK_F32X2(rp[2 * k],      rp[2 * k + 1],  accA[k]);
#pragma unroll
        for (int k = 0; k < 12; k++) UNPACK_F32X2(rp[24 + 2 * k], rp[25 + 2 * k], accB[k]);
    }
    __syncthreads();

    if (tid < 64) {
        const int q   = tid;                 // token 0..63
        const int lt  = q & 31;
        const int off = (q >> 5) * 24;
        float c[24];
#pragma unroll
        for (int k = 0; k < 24; k++) c[k] = rr[lt * 49 + off + k];
#pragma unroll
        for (int s2 = 1; s2 < 8; s2++) {
            const float* rp = rr + (s2 * 32 + lt) * 49 + off;
#pragma unroll
            for (int k = 0; k < 24; k++) c[k] += rp[k];
        }
        // write partials for this (token, split): 6 float4
        int tok = ((q & 3) << 11) + b0 + (q >> 2);      // m*2048 + b
        float4* pp = (float4*)(g_part + ((size_t)ds * NM * NB + tok) * 24);
#pragma unroll
        for (int k = 0; k < 6; k++)
            pp[k] = make_float4(c[4 * k], c[4 * k + 1], c[4 * k + 2], c[4 * k + 3]);
    }
}

// ---------------------------------------------------------------------------
// Reduce: sum 4 splits per token, gate winner, modality mean, head bias.
// 32 blocks x 256 threads = 8192 threads (one per token, lane groups of 4
// share b so the m-mean is a shuffle). ~3.1 MB read, ~2us.
// ---------------------------------------------------------------------------
__global__ void __launch_bounds__(256) reduce_kernel(
    const float* __restrict__ gate_b,
    const float* __restrict__ head_b,
    float* __restrict__ out)
{
    const int gt = blockIdx.x * 256 + threadIdx.x;   // 0..8191
    const int b  = gt >> 2;
    const int m  = gt & 3;
    const int tok = (m << 11) + b;

    float c[24];
    {
        const float4* p0 = (const float4*)(g_part + (size_t)tok * 24);
#pragma unroll
        for (int k = 0; k < 6; k++) {
            float4 v = p0[k];
            c[4 * k] = v.x; c[4 * k + 1] = v.y; c[4 * k + 2] = v.z; c[4 * k + 3] = v.w;
        }
#pragma unroll
        for (int sp = 1; sp < DSPLIT; sp++) {
            const float4* pp = (const float4*)(g_part + ((size_t)sp * NM * NB + tok) * 24);
#pragma unroll
            for (int k = 0; k < 6; k++) {
                float4 v = pp[k];
                c[4 * k]     += v.x; c[4 * k + 1] += v.y;
                c[4 * k + 2] += v.z; c[4 * k + 3] += v.w;
            }
        }
    }

    // gate logits (+bias); winner = max index among top-2 (ref semantics)
    float g[8];
#pragma unroll
    for (int e = 0; e < 8; e++) g[e] = c[e] + gate_b[e];
    int i1 = 0; float m1 = g[0];
#pragma unroll
    for (int e = 1; e < 8; e++) if (g[e] > m1) { m1 = g[e]; i1 = e; }
    int i2 = 0; float m2 = -3.402823466e38f;
#pragma unroll
    for (int e = 0; e < 8; e++) if (e != i1 && g[e] > m2) { m2 = g[e]; i2 = e; }
    int w = (i1 > i2) ? i1 : i2;

    float o0 = c[8 + (w << 1) + 0] + g_bdot[(w << 1) + 0];
    float o1 = c[8 + (w << 1) + 1] + g_bdot[(w << 1) + 1];

    // modality mean: lanes 4k..4k+3 share b, m = 0..3
    o0 += __shfl_down_sync(0xffffffffu, o0, 2);
    o0 += __shfl_down_sync(0xffffffffu, o0, 1);
    o1 += __shfl_down_sync(0xffffffffu, o1, 2);
    o1 += __shfl_down_sync(0xffffffffu, o1, 1);

    if (m == 0) {
        out[(b << 1) + 0] = 0.25f * o0 + head_b[0];
        out[(b << 1) + 1] = 0.25f * o1 + head_b[1];
    }
}

// ---------------------------------------------------------------------------
extern "C" void kernel_launch(void* const* d_in, const int* in_sizes, int n_in,
                              void* d_out, int out_size)
{
    const float* x        = (const float*)d_in[0];
    const float* gate_w   = (const float*)d_in[1];
    const float* gate_b   = (const float*)d_in[2];
    const float* expert_w = (const float*)d_in[3];
    const float* expert_b = (const float*)d_in[4];
    const float* head_w   = (const float*)d_in[5];
    const float* head_b   = (const float*)d_in[6];
    float* out = (float*)d_out;

    const size_t SMEM = (6144 + 2 * 64 * XSTR) * sizeof(float);   // 58,368 B
    cudaFuncSetAttribute(moe_main_kernel,
                         cudaFuncAttributeMaxDynamicSharedMemorySize, (int)SMEM);

    build_vtab_kernel<<<1024, 256>>>(expert_w, head_w, expert_b);
    moe_main_kernel<<<512, 256, SMEM>>>(x, gate_w);
    reduce_kernel<<<32, 256>>>(gate_b, head_b, out);
}

// round 8
// speedup vs baseline: 1.1526x; 1.0350x over previous
#include <cuda_runtime.h>
#include <cstdint>
#include <cstddef>

// Problem constants
#define NM 4
#define NB 2048
#define ND 1024
#define NE 8
#define NO 1024
#define NC 2

#define DSPLIT 2          // D split across blocks
#define DLOC   512        // d-columns per block
#define NCH    4          // chunks per block
#define CHC    128        // cols per chunk
#define XSTR   130        // x-tile row stride (floats); mod 32 == 2

// Scratch (no allocations allowed)
__device__ float g_vtab[ND * NE * NC];          // [d][e*2+c]  64 KB
__device__ float g_bdot[NE * NC];               // 16 floats
__device__ float g_part[DSPLIT * NM * NB * 24]; // partials [split][tok][24]

// packed f32x2 FMA (sm_100a+; ptxas never auto-fuses this)
#define FMA_F32X2(acc, a, b) \
    asm("fma.rn.f32x2 %0, %1, %2, %0;" : "+l"(acc) : "l"(a), "l"(b))
#define BCAST_F32X2(dst, f) \
    asm("mov.b64 %0, {%1, %1};" : "=l"(dst) : "f"(f))
#define UNPACK_F32X2(lo, hi, in) \
    asm("mov.b64 {%0, %1}, %2;" : "=f"(lo), "=f"(hi) : "l"(in))

// ---------------------------------------------------------------------------
// Pass A: V[e,d,c] = sum_o expert_w[e,d,o] * head_w[o,c]
// 1024 blocks x 256 threads, one row per warp. bdot fused. L2-hot ~4.5us.
// ---------------------------------------------------------------------------
__global__ void __launch_bounds__(256) build_vtab_kernel(
    const float* __restrict__ expert_w,
    const float* __restrict__ head_w,
    const float* __restrict__ expert_b)
{
    __shared__ float hw[NO * NC];  // [o*2+c]
    for (int i = threadIdx.x; i < NO * NC; i += 256) hw[i] = head_w[i];
    __syncthreads();

    const int lane = threadIdx.x & 31;
    const int wid  = threadIdx.x >> 5;
    const int r    = (blockIdx.x << 3) + wid;          // row = e*1024 + d

    const float4* row4 = (const float4*)(expert_w + ((size_t)r << 10));
    float4 w[8];
#pragma unroll
    for (int i = 0; i < 8; i++) w[i] = row4[i * 32 + lane];

    float a0 = 0.f, a1 = 0.f;
#pragma unroll
    for (int i = 0; i < 8; i++) {
        const float4* h = (const float4*)(hw + ((i * 128 + lane * 4) << 1));
        float4 h0 = h[0], h1 = h[1];
        a0 += w[i].x * h0.x + w[i].y * h0.z + w[i].z * h1.x + w[i].w * h1.z;
        a1 += w[i].x * h0.y + w[i].y * h0.w + w[i].z * h1.y + w[i].w * h1.w;
    }
#pragma unroll
    for (int off = 16; off; off >>= 1) {
        a0 += __shfl_down_sync(0xffffffffu, a0, off);
        a1 += __shfl_down_sync(0xffffffffu, a1, off);
    }
    if (lane == 0) {
        int e = r >> 10, d = r & 1023;
        g_vtab[(d << 4) + (e << 1) + 0] = a0;
        g_vtab[(d << 4) + (e << 1) + 1] = a1;
    }

    if (blockIdx.x < 8 && wid == 0) {
        int e = blockIdx.x;
        const float4* eb4 = ((const float4*)expert_b) + (e << 8);
        float b0 = 0.f, b1 = 0.f;
#pragma unroll
        for (int i = 0; i < 8; i++) {
            float4 bb = eb4[i * 32 + lane];
            const float4* h = (const float4*)(hw + ((i * 32 + lane) << 3));
            float4 h0 = h[0], h1 = h[1];
            b0 += bb.x * h0.x + bb.y * h0.z + bb.z * h1.x + bb.w * h1.z;
            b1 += bb.x * h0.y + bb.y * h0.w + bb.z * h1.y + bb.w * h1.w;
        }
#pragma unroll
        for (int off = 16; off; off >>= 1) {
            b0 += __shfl_down_sync(0xffffffffu, b0, off);
            b1 += __shfl_down_sync(0xffffffffu, b1, off);
        }
        if (lane == 0) { g_bdot[e * 2] = b0; g_bdot[e * 2 + 1] = b1; }
    }
}

// ---------------------------------------------------------------------------
// Main pass, round 8: round-5 inner loop UNCHANGED (2 tokens/thread,
// 12 broadcast LDS.128 -> 48 FFMA2), residency restructured:
// D-split 2, 256 blocks x 256 threads, 82 KB smem -> 2 blocks/SM =
// 16 warps in TWO INDEPENDENT barrier domains (staging of one block
// overlaps compute of the other). launch_bounds(256,2) -> 128-reg cap,
// above the 90 this loop measured (no spills).
//
// Block = 64 tokens (16 b x 4 m) x 512 d. Thread (s,t): s = tid>>5
// d-slice (8 x 64d), t = tid&31, tokens A=t, B=t+32. Partials (24/token)
// to g_part; reduce_kernel folds splits + winner + m-mean + head.
// ---------------------------------------------------------------------------
__global__ void __launch_bounds__(256, 2) moe_main_kernel(
    const float* __restrict__ x,
    const float* __restrict__ gate_w)
{
    extern __shared__ float sm[];
    float* ct = sm;                    // 12288 floats: [d_loc][24] = gate(8)|V(16)
    float* xs = sm + 12288;            // 64*130 = 8320 floats
    float* rr = sm;                    // fold buffer aliases (all dead by then)

    const int tid = threadIdx.x;
    const int tg  = blockIdx.x >> 1;        // token group 0..127
    const int ds  = blockIdx.x & 1;         // d-split 0..1
    const int b0  = tg << 4;                // 16 b-values
    const int dof = ds * DLOC;              // d offset
    const int t   = tid & 31;               // token lane (A=t, B=t+32)
    const int s   = tid >> 5;               // d-slice 0..7 (warp-uniform)

    // ---- fill table slice (coalesced float4): 512 d x 24 floats ----
    {
        const float4* gsrc = (const float4*)gate_w;     // [d][8] = 2 f4/row
        for (int i = tid; i < 1024; i += 256) {
            int d = i >> 1, h = i & 1;
            *(float4*)(ct + d * 24 + h * 4) = gsrc[((dof + d) << 1) + h];
        }
        const float4* vsrc = (const float4*)g_vtab;     // [d][16] = 4 f4/row
        for (int i = tid; i < 2048; i += 256) {
            int d = i >> 2, q = i & 3;
            *(float4*)(ct + d * 24 + 8 + q * 4) = vsrc[((dof + d) << 2) + q];
        }
    }

    unsigned long long accA[12], accB[12];
#pragma unroll
    for (int k = 0; k < 12; k++) { accA[k] = 0ull; accB[k] = 0ull; }

    for (int ch = 0; ch < NCH; ch++) {
        const int dc = dof + ch * CHC;
        __syncthreads();   // xs free (and table fill complete on 1st iter)
        // stage 64 rows x 128 cols (2048 float4 / 256 thr = 8 each)
        for (int v = tid; v < 2048; v += 256) {
            int r = v >> 5, c4 = v & 31;
            int row = ((r & 3) << 11) + b0 + (r >> 2);   // m*2048 + b0 + brel
            float4 t4 = *(const float4*)(x + ((size_t)row << 10) + dc + (c4 << 2));
            float* dst = xs + r * XSTR + (c4 << 2);
            *(float2*)(dst)     = make_float2(t4.x, t4.y);
            *(float2*)(dst + 2) = make_float2(t4.z, t4.w);
        }
        __syncthreads();   // xs visible

        const float* xA = xs + t * XSTR + (s << 4);
        const float* xB = xA + 32 * XSTR;
        const int dl0 = (ch << 7) + (s << 4);            // local d base
#pragma unroll
        for (int j = 0; j < 16; j += 2) {
            float2 xa = *(const float2*)(xA + j);
            float2 xb = *(const float2*)(xB + j);
            unsigned long long a0, a1, bp0, bp1;
            BCAST_F32X2(a0, xa.x);  BCAST_F32X2(a1, xa.y);
            BCAST_F32X2(bp0, xb.x); BCAST_F32X2(bp1, xb.y);
            const ulonglong2* c0 = (const ulonglong2*)(ct + (dl0 + j) * 24);
            const ulonglong2* c1 = (const ulonglong2*)(ct + (dl0 + j + 1) * 24);
            {
                ulonglong2 p0 = c0[0], p1 = c0[1], p2 = c0[2];
                ulonglong2 p3 = c0[3], p4 = c0[4], p5 = c0[5];
                FMA_F32X2(accA[0],  a0, p0.x); FMA_F32X2(accA[1],  a0, p0.y);
                FMA_F32X2(accA[2],  a0, p1.x); FMA_F32X2(accA[3],  a0, p1.y);
                FMA_F32X2(accA[4],  a0, p2.x); FMA_F32X2(accA[5],  a0, p2.y);
                FMA_F32X2(accA[6],  a0, p3.x); FMA_F32X2(accA[7],  a0, p3.y);
                FMA_F32X2(accA[8],  a0, p4.x); FMA_F32X2(accA[9],  a0, p4.y);
                FMA_F32X2(accA[10], a0, p5.x); FMA_F32X2(accA[11], a0, p5.y);
                FMA_F32X2(accB[0],  bp0, p0.x); FMA_F32X2(accB[1],  bp0, p0.y);
                FMA_F32X2(accB[2],  bp0, p1.x); FMA_F32X2(accB[3],  bp0, p1.y);
                FMA_F32X2(accB[4],  bp0, p2.x); FMA_F32X2(accB[5],  bp0, p2.y);
                FMA_F32X2(accB[6],  bp0, p3.x); FMA_F32X2(accB[7],  bp0, p3.y);
                FMA_F32X2(accB[8],  bp0, p4.x); FMA_F32X2(accB[9],  bp0, p4.y);
                FMA_F32X2(accB[10], bp0, p5.x); FMA_F32X2(accB[11], bp0, p5.y);
            }
            {
                ulonglong2 q0 = c1[0], q1 = c1[1], q2 = c1[2];
                ulonglong2 q3 = c1[3], q4 = c1[4], q5 = c1[5];
                FMA_F32X2(accA[0],  a1, q0.x); FMA_F32X2(accA[1],  a1, q0.y);
                FMA_F32X2(accA[2],  a1, q1.x); FMA_F32X2(accA[3],  a1, q1.y);
                FMA_F32X2(accA[4],  a1, q2.x); FMA_F32X2(accA[5],  a1, q2.y);
                FMA_F32X2(accA[6],  a1, q3.x); FMA_F32X2(accA[7],  a1, q3.y);
                FMA_F32X2(accA[8],  a1, q4.x); FMA_F32X2(accA[9],  a1, q4.y);
                FMA_F32X2(accA[10], a1, q5.x); FMA_F32X2(accA[11], a1, q5.y);
                FMA_F32X2(accB[0],  bp1, q0.x); FMA_F32X2(accB[1],  bp1, q0.y);
                FMA_F32X2(accB[2],  bp1, q1.x); FMA_F32X2(accB[3],  bp1, q1.y);
                FMA_F32X2(accB[4],  bp1, q2.x); FMA_F32X2(accB[5],  bp1, q2.y);
                FMA_F32X2(accB[6],  bp1, q3.x); FMA_F32X2(accB[7],  bp1, q3.y);
                FMA_F32X2(accB[8],  bp1, q4.x); FMA_F32X2(accB[9],  bp1, q4.y);
                FMA_F32X2(accB[10], bp1, q5.x); FMA_F32X2(accB[11], bp1, q5.y);
            }
        }
    }

    // ---- fold 8 slices via smem (rr aliases table + x tile, both dead) ----
    __syncthreads();
    {
        float* rp = rr + (s * 32 + t) * 49;
#pragma unroll
        for (int k = 0; k < 12; k++) UNPACK_F32X2(rp[2 * k],      rp[2 * k + 1],  accA[k]);
#pragma unroll
        for (int k = 0; k < 12; k++) UNPACK_F32X2(rp[24 + 2 * k], rp[25 + 2 * k], accB[k]);
    }
    __syncthreads();

    if (tid < 64) {
        const int q   = tid;                 // token 0..63
        const int lt  = q & 31;
        const int off = (q >> 5) * 24;
        float c[24];
#pragma unroll
        for (int k = 0; k < 24; k++) c[k] = rr[lt * 49 + off + k];
#pragma unroll
        for (int s2 = 1; s2 < 8; s2++) {
            const float* rp = rr + (s2 * 32 + lt) * 49 + off;
#pragma unroll
            for (int k = 0; k < 24; k++) c[k] += rp[k];
        }
        int tok = ((q & 3) << 11) + b0 + (q >> 2);      // m*2048 + b
        float4* pp = (float4*)(g_part + ((size_t)ds * NM * NB + tok) * 24);
#pragma unroll
        for (int k = 0; k < 6; k++)
            pp[k] = make_float4(c[4 * k], c[4 * k + 1], c[4 * k + 2], c[4 * k + 3]);
    }
}

// ---------------------------------------------------------------------------
// Reduce: sum splits per token, gate winner, modality mean, head bias.
// 32 blocks x 256 threads; lane groups of 4 share b -> m-mean via shuffle.
// ---------------------------------------------------------------------------
__global__ void __launch_bounds__(256) reduce_kernel(
    const float* __restrict__ gate_b,
    const float* __restrict__ head_b,
    float* __restrict__ out)
{
    const int gt = blockIdx.x * 256 + threadIdx.x;   // 0..8191
    const int b  = gt >> 2;
    const int m  = gt & 3;
    const int tok = (m << 11) + b;

    float c[24];
    {
        const float4* p0 = (const float4*)(g_part + (size_t)tok * 24);
#pragma unroll
        for (int k = 0; k < 6; k++) {
            float4 v = p0[k];
            c[4 * k] = v.x; c[4 * k + 1] = v.y; c[4 * k + 2] = v.z; c[4 * k + 3] = v.w;
        }
#pragma unroll
        for (int sp = 1; sp < DSPLIT; sp++) {
            const float4* pp = (const float4*)(g_part + ((size_t)sp * NM * NB + tok) * 24);
#pragma unroll
            for (int k = 0; k < 6; k++) {
                float4 v = pp[k];
                c[4 * k]     += v.x; c[4 * k + 1] += v.y;
                c[4 * k + 2] += v.z; c[4 * k + 3] += v.w;
            }
        }
    }

    // gate logits (+bias); winner = max index among top-2 (ref semantics)
    float g[8];
#pragma unroll
    for (int e = 0; e < 8; e++) g[e] = c[e] + gate_b[e];
    int i1 = 0; float m1 = g[0];
#pragma unroll
    for (int e = 1; e < 8; e++) if (g[e] > m1) { m1 = g[e]; i1 = e; }
    int i2 = 0; float m2 = -3.402823466e38f;
#pragma unroll
    for (int e = 0; e < 8; e++) if (e != i1 && g[e] > m2) { m2 = g[e]; i2 = e; }
    int w = (i1 > i2) ? i1 : i2;

    float o0 = c[8 + (w << 1) + 0] + g_bdot[(w << 1) + 0];
    float o1 = c[8 + (w << 1) + 1] + g_bdot[(w << 1) + 1];

    // modality mean: lanes 4k..4k+3 share b, m = 0..3
    o0 += __shfl_down_sync(0xffffffffu, o0, 2);
    o0 += __shfl_down_sync(0xffffffffu, o0, 1);
    o1 += __shfl_down_sync(0xffffffffu, o1, 2);
    o1 += __shfl_down_sync(0xffffffffu, o1, 1);

    if (m == 0) {
        out[(b << 1) + 0] = 0.25f * o0 + head_b[0];
        out[(b << 1) + 1] = 0.25f * o1 + head_b[1];
    }
}

// ---------------------------------------------------------------------------
extern "C" void kernel_launch(void* const* d_in, const int* in_sizes, int n_in,
                              void* d_out, int out_size)
{
    const float* x        = (const float*)d_in[0];
    const float* gate_w   = (const float*)d_in[1];
    const float* gate_b   = (const float*)d_in[2];
    const float* expert_w = (const float*)d_in[3];
    const float* expert_b = (const float*)d_in[4];
    const float* head_w   = (const float*)d_in[5];
    const float* head_b   = (const float*)d_in[6];
    float* out = (float*)d_out;

    const size_t SMEM = (12288 + 64 * XSTR) * sizeof(float);   // 82,432 B
    cudaFuncSetAttribute(moe_main_kernel,
                         cudaFuncAttributeMaxDynamicSharedMemorySize, (int)SMEM);

    build_vtab_kernel<<<1024, 256>>>(expert_w, head_w, expert_b);
    moe_main_kernel<<<256, 256, SMEM>>>(x, gate_w);
    reduce_kernel<<<32, 256>>>(gate_b, head_b, out);
}